// round 3
// baseline (speedup 1.0000x reference)
#include <cuda_runtime.h>
#include <cstdint>

#define BB 1024
#define FF 4
#define MM 512
#define DD 8192
#define RITERS 10

// ---------------- device scratch (no allocations allowed) ----------------
__device__ int8_t g_inp8[BB * DD];                    // 8 MB   input signs
__device__ int8_t g_est [BB * FF * DD];               // 32 MB  current estimates (int8 +-1)
__device__ int8_t g_X   [BB * FF * DD];               // 32 MB  stage input to GEMM1
__device__ int8_t g_C1  [FF * MM * DD];               // 16 MB  codebook signs, [f][m][d]
__device__ int8_t g_B2  [(size_t)FF * DD * 1024];     // 32 MB  stacked transposed codebook [f][d][k]
__device__ int8_t g_A2  [BB * FF * 1024];             // 4 MB   sim split planes [b][f][k]
__device__ int    g_sim [BB * FF * MM];               // 8 MB   final sim
__device__ int    g_notconv[RITERS];

// ---------------- small kernels ----------------
__global__ void k_reset() {
    if (threadIdx.x < RITERS) g_notconv[threadIdx.x] = 0;
}

// which: 0 -> g_inp8, 1 -> g_est, 2 -> g_C1
__global__ void k_cvt(const float* __restrict__ src, int n4, int which) {
    int t = blockIdx.x * blockDim.x + threadIdx.x;
    if (t >= n4) return;
    float4 v = ((const float4*)src)[t];
    char4 c;
    c.x = (v.x >= 0.f) ? 1 : -1;
    c.y = (v.y >= 0.f) ? 1 : -1;
    c.z = (v.z >= 0.f) ? 1 : -1;
    c.w = (v.w >= 0.f) ? 1 : -1;
    int8_t* dst = (which == 0) ? g_inp8 : (which == 1) ? g_est : g_C1;
    ((char4*)dst)[t] = c;
}

// build B2[f][d][k]: k<512 -> 127*sign(C[f][k][d]), k>=512 -> sign(C[f][k-512][d])
__global__ void k_build_b2(const float* __restrict__ code) {
    __shared__ int8_t s[32][33];
    int f = blockIdx.z;
    int m0 = blockIdx.x * 32;
    int d0 = blockIdx.y * 32;
    int tx = threadIdx.x;   // 0..31
    int ty = threadIdx.y;   // 0..7
#pragma unroll
    for (int r = 0; r < 4; r++) {
        int m = m0 + ty + r * 8;
        float v = code[((size_t)(f * MM + m)) * DD + d0 + tx];
        s[ty + r * 8][tx] = (v >= 0.f) ? 1 : -1;
    }
    __syncthreads();
#pragma unroll
    for (int r = 0; r < 4; r++) {
        int d = d0 + ty + r * 8;
        int8_t v = s[tx][ty + r * 8];            // s[m_local][d_local]
        size_t base = ((size_t)f * DD + d) * 1024;
        g_B2[base + m0 + tx]       = (int8_t)(v * 127);
        g_B2[base + 512 + m0 + tx] = v;
    }
}

// X[b][f][d] = input * prod_f'(est) * est_f  (sign algebra on packed bytes)
__global__ void k_stage_x() {
    int t = blockIdx.x * blockDim.x + threadIdx.x;
    if (t >= BB * DD / 4) return;
    int b = t / (DD / 4);
    int dq = t % (DD / 4);
    const uint32_t* inpw = (const uint32_t*)g_inp8;
    const uint32_t* estw = (const uint32_t*)g_est;
    uint32_t* xw = (uint32_t*)g_X;
    uint32_t wi = inpw[(size_t)b * (DD / 4) + dq];
    uint32_t e[FF];
#pragma unroll
    for (int f = 0; f < FF; f++)
        e[f] = estw[((size_t)(b * FF + f)) * (DD / 4) + dq];
    uint32_t q = wi ^ e[0] ^ e[1] ^ e[2] ^ e[3];
#pragma unroll
    for (int f = 0; f < FF; f++) {
        uint32_t tt = q ^ e[f];                 // est_f appears twice -> removed
        uint32_t mm = (tt >> 7) & 0x01010101u;  // per-byte sign bits
        uint32_t r  = __vsub4(0x01010101u, mm << 1);  // +1 or -1 per byte
        xw[((size_t)(b * FF + f)) * (DD / 4) + dq] = r;
    }
}

// ---------------- int8 GEMM (mma.sync m16n8k32) ----------------
#define BLK_M 128
#define BLK_N 64
#define BLK_K 64
#define AST 80
#define BST 80

__device__ __forceinline__ void mma_s8(int* c, const uint32_t* a, const uint32_t* b) {
    asm volatile(
        "mma.sync.aligned.m16n8k32.row.col.s32.s8.s8.s32 "
        "{%0,%1,%2,%3}, {%4,%5,%6,%7}, {%8,%9}, {%0,%1,%2,%3};\n"
        : "+r"(c[0]), "+r"(c[1]), "+r"(c[2]), "+r"(c[3])
        : "r"(a[0]), "r"(a[1]), "r"(a[2]), "r"(a[3]), "r"(b[0]), "r"(b[1]));
}

// MODE 1: sim = X*C^T, epilogue splits sim -> A2 planes
// MODE 2: sim = est*C^T, epilogue writes g_sim (final)
// MODE 3: Y = A2*B2^T, epilogue sign -> g_est, convergence flag
template <int MODE>
__global__ void __launch_bounds__(256, 1) k_gemm(int it) {
    __shared__ int8_t ash[2][BLK_M * AST];
    __shared__ int8_t bsh[2][BLK_N * BST];
    __shared__ int sdiff;

    const int tid = threadIdx.x;
    const int lane = tid & 31;
    const int wid = tid >> 5;
    const int wm = wid >> 1, wn = wid & 1;
    const int f = blockIdx.z;
    const int rowBase = blockIdx.y * BLK_M;
    const int colBase = blockIdx.x * BLK_N;

    const int8_t* Ap;
    const int8_t* Bp;
    int lda, ldb;
    constexpr int K = (MODE == 3) ? 1024 : DD;
    if (MODE == 1)      { Ap = g_X   + (size_t)f * DD;   lda = FF * DD;   Bp = g_C1 + (size_t)f * MM * DD; ldb = DD; }
    else if (MODE == 2) { Ap = g_est + (size_t)f * DD;   lda = FF * DD;   Bp = g_C1 + (size_t)f * MM * DD; ldb = DD; }
    else                { Ap = g_A2  + f * 1024;         lda = FF * 1024; Bp = g_B2 + (size_t)f * DD * 1024; ldb = 1024; }

    if (tid == 0) sdiff = 0;

    auto load_stage = [&](int s, int k0) {
#pragma unroll
        for (int c = 0; c < 2; c++) {
            int ch = tid + c * 256;           // 512 chunks of 16B for A
            int r = ch >> 2, seg = ch & 3;
            const int8_t* g = Ap + (size_t)(rowBase + r) * lda + k0 + seg * 16;
            uint32_t sa = (uint32_t)__cvta_generic_to_shared(&ash[s][r * AST + seg * 16]);
            asm volatile("cp.async.cg.shared.global [%0], [%1], 16;\n" :: "r"(sa), "l"(g));
        }
        {
            int ch = tid;                     // 256 chunks of 16B for B
            int r = ch >> 2, seg = ch & 3;
            const int8_t* g = Bp + (size_t)(colBase + r) * ldb + k0 + seg * 16;
            uint32_t sa = (uint32_t)__cvta_generic_to_shared(&bsh[s][r * BST + seg * 16]);
            asm volatile("cp.async.cg.shared.global [%0], [%1], 16;\n" :: "r"(sa), "l"(g));
        }
        asm volatile("cp.async.commit_group;\n");
    };

    int acc[2][4][4];
#pragma unroll
    for (int mi = 0; mi < 2; mi++)
#pragma unroll
        for (int ni = 0; ni < 4; ni++)
#pragma unroll
            for (int j = 0; j < 4; j++) acc[mi][ni][j] = 0;

    constexpr int KC = K / BLK_K;
    load_stage(0, 0);
#pragma unroll 1
    for (int kc = 0; kc < KC; kc++) {
        if (kc + 1 < KC) {
            load_stage((kc + 1) & 1, (kc + 1) * BLK_K);
            asm volatile("cp.async.wait_group 1;\n");
        } else {
            asm volatile("cp.async.wait_group 0;\n");
        }
        __syncthreads();
        const int8_t* as = ash[kc & 1];
        const int8_t* bs = bsh[kc & 1];
#pragma unroll
        for (int ks = 0; ks < 2; ks++) {
            const int koff = ks * 32;
            uint32_t afr[2][4], bfr[4][2];
            const int co = koff + (lane & 3) * 4;
#pragma unroll
            for (int mi = 0; mi < 2; mi++) {
                int r0 = wm * 32 + mi * 16 + (lane >> 2);
                afr[mi][0] = *(const uint32_t*)(as + r0 * AST + co);
                afr[mi][1] = *(const uint32_t*)(as + (r0 + 8) * AST + co);
                afr[mi][2] = *(const uint32_t*)(as + r0 * AST + co + 16);
                afr[mi][3] = *(const uint32_t*)(as + (r0 + 8) * AST + co + 16);
            }
#pragma unroll
            for (int ni = 0; ni < 4; ni++) {
                int c0 = wn * 32 + ni * 8 + (lane >> 2);
                bfr[ni][0] = *(const uint32_t*)(bs + c0 * BST + co);
                bfr[ni][1] = *(const uint32_t*)(bs + c0 * BST + co + 16);
            }
#pragma unroll
            for (int mi = 0; mi < 2; mi++)
#pragma unroll
                for (int ni = 0; ni < 4; ni++)
                    mma_s8(acc[mi][ni], afr[mi], bfr[ni]);
        }
        __syncthreads();
    }

    // ---------------- epilogue ----------------
    int mydiff = 0;
#pragma unroll
    for (int mi = 0; mi < 2; mi++) {
#pragma unroll
        for (int ni = 0; ni < 4; ni++) {
            int r0 = rowBase + wm * 32 + mi * 16 + (lane >> 2);
            int c0 = colBase + wn * 32 + ni * 8 + (lane & 3) * 2;
#pragma unroll
            for (int j = 0; j < 4; j++) {
                int rr = r0 + ((j >= 2) ? 8 : 0);
                int cc = c0 + (j & 1);
                int s = acc[mi][ni][j];
                if (MODE == 1) {
                    int aa = (s >= 0) ? (s + 63) / 127 : -((63 - s) / 127);
                    int rb = s - 127 * aa;
                    size_t base = ((size_t)rr * FF + f) * 1024;
                    g_A2[base + cc] = (int8_t)aa;
                    g_A2[base + 512 + cc] = (int8_t)rb;
                } else if (MODE == 2) {
                    g_sim[((size_t)rr * FF + f) * MM + cc] = s;
                } else {
                    int8_t s8 = (s >= 0) ? (int8_t)1 : (int8_t)(-1);
                    size_t idx = ((size_t)rr * FF + f) * DD + cc;
                    if (g_est[idx] != s8) mydiff = 1;
                    g_est[idx] = s8;
                }
            }
        }
    }
    if (MODE == 3) {
        if (mydiff) sdiff = 1;   // benign race, same value
        __syncthreads();
        if (tid == 0 && sdiff) atomicOr(&g_notconv[it], 1);
    }
}

// ---------------- finalize: argmax(|sim|) first-index + k ----------------
__global__ void k_final(float* __restrict__ out) {
    int gt = blockIdx.x * blockDim.x + threadIdx.x;
    int w = gt >> 5;
    int lane = gt & 31;
    if (w < BB * FF) {
        const int* srow = g_sim + (size_t)w * MM;
        int bestv = -1, bestm = 0;
#pragma unroll
        for (int j = 0; j < MM / 32; j++) {
            int m = j * 32 + lane;
            int v = srow[m];
            v = (v < 0) ? -v : v;
            if (v > bestv) { bestv = v; bestm = m; }
        }
#pragma unroll
        for (int o = 16; o; o >>= 1) {
            int ov = __shfl_down_sync(0xFFFFFFFFu, bestv, o);
            int om = __shfl_down_sync(0xFFFFFFFFu, bestm, o);
            if (ov > bestv || (ov == bestv && om < bestm)) { bestv = ov; bestm = om; }
        }
        if (lane == 0) out[w] = (float)bestm;
    }
    if (blockIdx.x == 0 && threadIdx.x == 0) {
        int k = 0;
        bool done = false;
#pragma unroll
        for (int i = 0; i < RITERS; i++) {
            if (!done) k++;
            if (g_notconv[i] == 0) done = true;
        }
        out[BB * FF] = (float)k;
    }
}

// est -> float output. NOTE: output starts at float offset BB*FF+1 = 4097,
// i.e. byte offset 16388 which is only 4B-aligned. Scalar STG.32 only.
__global__ void k_est_out(float* __restrict__ out) {
    int t = blockIdx.x * blockDim.x + threadIdx.x;
    if (t >= BB * FF * DD / 4) return;
    char4 v = ((const char4*)g_est)[t];
    float* o = out + (size_t)(BB * FF) + 1 + (size_t)t * 4;
    o[0] = (float)v.x;
    o[1] = (float)v.y;
    o[2] = (float)v.z;
    o[3] = (float)v.w;
}

// ---------------- launch ----------------
extern "C" void kernel_launch(void* const* d_in, const int* in_sizes, int n_in,
                              void* d_out, int out_size) {
    const float* inp  = (const float*)d_in[0];
    const float* init = (const float*)d_in[1];
    const float* code = (const float*)d_in[2];
    float* out = (float*)d_out;

    k_reset<<<1, 32>>>();
    k_cvt<<<(BB * DD / 4 + 255) / 256, 256>>>(inp, BB * DD / 4, 0);
    k_cvt<<<(BB * FF * DD / 4 + 255) / 256, 256>>>(init, BB * FF * DD / 4, 1);
    k_cvt<<<(FF * MM * DD / 4 + 255) / 256, 256>>>(code, FF * MM * DD / 4, 2);
    k_build_b2<<<dim3(MM / 32, DD / 32, FF), dim3(32, 8)>>>(code);

    for (int it = 0; it < RITERS; it++) {
        k_stage_x<<<(BB * DD / 4 + 255) / 256, 256>>>();
        k_gemm<1><<<dim3(MM / BLK_N, BB / BLK_M, FF), 256>>>(0);
        k_gemm<3><<<dim3(DD / BLK_N, BB / BLK_M, FF), 256>>>(it);
    }
    k_gemm<2><<<dim3(MM / BLK_N, BB / BLK_M, FF), 256>>>(0);
    k_final<<<(BB * FF * 32 + 255) / 256, 256>>>(out);
    k_est_out<<<(BB * FF * DD / 4 + 255) / 256, 256>>>(out);
}

// round 5
// speedup vs baseline: 1.2741x; 1.2741x over previous
#include <cuda_runtime.h>
#include <cuda_bf16.h>
#include <cstdint>

#define BB 1024
#define FF 4
#define MM 512
#define DD 8192
#define RITERS 10

// ---------------- device scratch (no allocations allowed) ----------------
__device__ __nv_bfloat16 g_inp[BB * DD];                  // 16 MB input signs
__device__ __nv_bfloat16 g_est[BB * FF * DD];             // 64 MB estimates (+-1)
__device__ __nv_bfloat16 g_X  [BB * FF * DD];             // 64 MB stage input
__device__ __nv_bfloat16 g_C1 [FF * MM * DD];             // 32 MB codebook signs [f][m][d]
__device__ __nv_bfloat16 g_B2 [(size_t)FF * DD * 1024];   // 64 MB stacked codebook [f][d][k] (+-128 | +-1)
__device__ __nv_bfloat16 g_A2 [BB * FF * 1024];           // 8 MB  sim split digits [b][f][k]
__device__ float         g_sim[BB * FF * MM];             // 8 MB  final sim
__device__ int           g_notconv[RITERS];

__device__ __forceinline__ uint32_t sgn_bf16(float v) { return (v >= 0.f) ? 0x3F80u : 0xBF80u; }
__device__ __forceinline__ uint32_t bf16bits(int v) {
    __nv_bfloat16 h = __float2bfloat16((float)v);
    return (uint32_t)*reinterpret_cast<unsigned short*>(&h);
}

// ---------------- small kernels ----------------
__global__ void k_reset() {
    if (threadIdx.x < RITERS) g_notconv[threadIdx.x] = 0;
}

// input + init_estimates -> bf16 signs
__global__ void k_cvt_ie(const float* __restrict__ inp, const float* __restrict__ init,
                         int n_inp4, int n_est4) {
    int t = blockIdx.x * blockDim.x + threadIdx.x;
    if (t < n_inp4) {
        float4 v = ((const float4*)inp)[t];
        uint2 w;
        w.x = sgn_bf16(v.x) | (sgn_bf16(v.y) << 16);
        w.y = sgn_bf16(v.z) | (sgn_bf16(v.w) << 16);
        ((uint2*)g_inp)[t] = w;
    } else if (t < n_inp4 + n_est4) {
        int u = t - n_inp4;
        float4 v = ((const float4*)init)[u];
        uint2 w;
        w.x = sgn_bf16(v.x) | (sgn_bf16(v.y) << 16);
        w.y = sgn_bf16(v.z) | (sgn_bf16(v.w) << 16);
        ((uint2*)g_est)[u] = w;
    }
}

// codebook -> C1 [f][m][d] signs AND B2 [f][d][k] (k<512: +-128, k>=512: +-1)
__global__ void k_cvt_code(const float* __restrict__ code) {
    __shared__ unsigned short s[32][33];
    int f = blockIdx.z;
    int m0 = blockIdx.x * 32;
    int d0 = blockIdx.y * 32;
    int tx = threadIdx.x;   // 0..31 (d)
    int ty = threadIdx.y;   // 0..7
#pragma unroll
    for (int r = 0; r < 4; r++) {
        int m = m0 + ty + r * 8;
        float v = code[((size_t)(f * MM + m)) * DD + d0 + tx];
        unsigned short sg = (v >= 0.f) ? 0x3F80u : 0xBF80u;
        s[ty + r * 8][tx] = sg;
        *(unsigned short*)&g_C1[((size_t)(f * MM + m)) * DD + d0 + tx] = sg;
    }
    __syncthreads();
#pragma unroll
    for (int r = 0; r < 4; r++) {
        int d = d0 + ty + r * 8;
        unsigned short sg = s[tx][ty + r * 8];     // sign of C[f][m0+tx][d]
        unsigned short neg = sg >> 15;
        size_t base = ((size_t)f * DD + d) * 1024;
        *(unsigned short*)&g_B2[base + m0 + tx]       = neg ? 0xC300u : 0x4300u;  // +-128
        *(unsigned short*)&g_B2[base + 512 + m0 + tx] = sg;                        // +-1
    }
}

// X[b][f][d] = input * prod_all * est_f  (sign-bit algebra on packed bf16 pairs)
__global__ void k_stage_x() {
    int t = blockIdx.x * blockDim.x + threadIdx.x;
    if (t >= BB * DD / 4) return;
    int b = t / (DD / 4);
    int dq = t % (DD / 4);
    const uint2* inp2 = (const uint2*)g_inp;
    const uint2* est2 = (const uint2*)g_est;
    uint2* x2 = (uint2*)g_X;
    uint2 wi = inp2[(size_t)b * (DD / 4) + dq];
    uint2 e[FF];
#pragma unroll
    for (int f = 0; f < FF; f++)
        e[f] = est2[((size_t)(b * FF + f)) * (DD / 4) + dq];
    uint32_t qx = wi.x ^ e[0].x ^ e[1].x ^ e[2].x ^ e[3].x;
    uint32_t qy = wi.y ^ e[0].y ^ e[1].y ^ e[2].y ^ e[3].y;
#pragma unroll
    for (int f = 0; f < FF; f++) {
        uint2 r;
        r.x = ((qx ^ e[f].x) & 0x80008000u) | 0x3F803F80u;
        r.y = ((qy ^ e[f].y) & 0x80008000u) | 0x3F803F80u;
        x2[((size_t)(b * FF + f)) * (DD / 4) + dq] = r;
    }
}

// ---------------- bf16 mma.sync GEMM: D[128x128] = A[128xK] * B[128xK]^T ----------------
// MODE 1: sim = X*C1^T   (K=8192), epilogue 128-split -> g_A2
// MODE 2: sim = est*C1^T (K=8192), epilogue -> g_sim (float)
// MODE 3: Y  = A2*B2^T   (K=1024), epilogue sign -> g_est + conv flag
#define BLK_M 128
#define BLK_N 128
#define RSTRIDE 144                    // 64 bf16 = 128B data + 16B pad (conflict-free)
#define A_SZ (BLK_M * RSTRIDE)
#define B_SZ (BLK_N * RSTRIDE)
#define STG_SZ (A_SZ + B_SZ)
#define SMEM_DYN (2 * STG_SZ)

__device__ __forceinline__ void mma_bf16(float* c, const uint32_t* a, const uint32_t* b) {
    asm volatile(
        "mma.sync.aligned.m16n8k16.row.col.f32.bf16.bf16.f32 "
        "{%0,%1,%2,%3}, {%4,%5,%6,%7}, {%8,%9}, {%0,%1,%2,%3};\n"
        : "+f"(c[0]), "+f"(c[1]), "+f"(c[2]), "+f"(c[3])
        : "r"(a[0]), "r"(a[1]), "r"(a[2]), "r"(a[3]), "r"(b[0]), "r"(b[1]));
}

template <int MODE>
__global__ void __launch_bounds__(256, 2) k_gemm(int it) {
    extern __shared__ char dsm[];
    __shared__ int sdiff;
    char* ash = dsm;                        // [2][A_SZ] interleaved with B
    const int tid = threadIdx.x;
    const int lane = tid & 31;
    const int wid = tid >> 5;
    const int wm = wid >> 1, wn = wid & 1;  // 4 x 2 warps; warp tile 32 x 64
    const int f = blockIdx.z;
    const int rowBase = blockIdx.y * BLK_M;
    const int colBase = blockIdx.x * BLK_N;

    const char* Ap;
    const char* Bp;
    size_t ldaB, ldbB;
    constexpr int K = (MODE == 3) ? 1024 : DD;
    constexpr int KC = K / 64;
    if (MODE == 1)      { Ap = (const char*)(g_X   + (size_t)f * DD);        ldaB = (size_t)FF * DD * 2;
                          Bp = (const char*)(g_C1  + (size_t)f * MM * DD);   ldbB = (size_t)DD * 2; }
    else if (MODE == 2) { Ap = (const char*)(g_est + (size_t)f * DD);        ldaB = (size_t)FF * DD * 2;
                          Bp = (const char*)(g_C1  + (size_t)f * MM * DD);   ldbB = (size_t)DD * 2; }
    else                { Ap = (const char*)(g_A2  + (size_t)f * 1024);      ldaB = (size_t)FF * 1024 * 2;
                          Bp = (const char*)(g_B2  + (size_t)f * DD * 1024); ldbB = 1024 * 2; }

    if (tid == 0) sdiff = 0;

    auto load_stage = [&](int s, int c) {
        const size_t k0 = (size_t)c * 128;            // bytes
        char* ab = ash + s * STG_SZ;
        char* bb = ab + A_SZ;
#pragma unroll
        for (int i = 0; i < 4; i++) {                 // A: 1024 chunks of 16B
            int cid = tid + i * 256;
            int r = cid >> 3, sg = cid & 7;
            const char* g = Ap + (size_t)(rowBase + r) * ldaB + k0 + sg * 16;
            uint32_t sa = (uint32_t)__cvta_generic_to_shared(ab + r * RSTRIDE + sg * 16);
            asm volatile("cp.async.cg.shared.global [%0], [%1], 16;" :: "r"(sa), "l"(g));
        }
#pragma unroll
        for (int i = 0; i < 4; i++) {                 // B: 1024 chunks of 16B
            int cid = tid + i * 256;
            int r = cid >> 3, sg = cid & 7;
            const char* g = Bp + (size_t)(colBase + r) * ldbB + k0 + sg * 16;
            uint32_t sa = (uint32_t)__cvta_generic_to_shared(bb + r * RSTRIDE + sg * 16);
            asm volatile("cp.async.cg.shared.global [%0], [%1], 16;" :: "r"(sa), "l"(g));
        }
        asm volatile("cp.async.commit_group;");
    };

    float acc[2][8][4];
#pragma unroll
    for (int mi = 0; mi < 2; mi++)
#pragma unroll
        for (int ni = 0; ni < 8; ni++)
#pragma unroll
            for (int j = 0; j < 4; j++) acc[mi][ni][j] = 0.f;

    load_stage(0, 0);
#pragma unroll 1
    for (int c = 0; c < KC; c++) {
        const int s = c & 1;
        if (c + 1 < KC) {
            load_stage(s ^ 1, c + 1);
            asm volatile("cp.async.wait_group 1;");
        } else {
            asm volatile("cp.async.wait_group 0;");
        }
        __syncthreads();
        const char* as = ash + s * STG_SZ;
        const char* bs = as + A_SZ;
#pragma unroll
        for (int ks = 0; ks < 4; ks++) {              // 4 x k16 per 64-elem chunk
            const int co = ks * 32 + (lane & 3) * 4;  // byte offset in row
            uint32_t afr[2][4], bfr[8][2];
#pragma unroll
            for (int mi = 0; mi < 2; mi++) {
                int r0 = wm * 32 + mi * 16 + (lane >> 2);
                afr[mi][0] = *(const uint32_t*)(as + r0 * RSTRIDE + co);
                afr[mi][1] = *(const uint32_t*)(as + (r0 + 8) * RSTRIDE + co);
                afr[mi][2] = *(const uint32_t*)(as + r0 * RSTRIDE + co + 16);
                afr[mi][3] = *(const uint32_t*)(as + (r0 + 8) * RSTRIDE + co + 16);
            }
#pragma unroll
            for (int ni = 0; ni < 8; ni++) {
                int c0 = wn * 64 + ni * 8 + (lane >> 2);
                bfr[ni][0] = *(const uint32_t*)(bs + c0 * RSTRIDE + co);
                bfr[ni][1] = *(const uint32_t*)(bs + c0 * RSTRIDE + co + 16);
            }
#pragma unroll
            for (int mi = 0; mi < 2; mi++)
#pragma unroll
                for (int ni = 0; ni < 8; ni++)
                    mma_bf16(acc[mi][ni], afr[mi], bfr[ni]);
        }
        __syncthreads();
    }

    // ---------------- epilogue (packed 4B/8B coalesced stores) ----------------
    int mydiff = 0;
#pragma unroll
    for (int mi = 0; mi < 2; mi++) {
#pragma unroll
        for (int ni = 0; ni < 8; ni++) {
            const int r0 = rowBase + wm * 32 + mi * 16 + (lane >> 2);
            const int c0 = colBase + wn * 64 + ni * 8 + (lane & 3) * 2;
#pragma unroll
            for (int h = 0; h < 2; h++) {             // row halves (+0, +8)
                const int rr = r0 + h * 8;
                const float v0 = acc[mi][ni][2 * h];
                const float v1 = acc[mi][ni][2 * h + 1];
                if (MODE == 1) {
                    int s0 = __float2int_rn(v0);
                    int s1 = __float2int_rn(v1);
                    int a0 = (s0 + 64) >> 7, b0 = s0 - (a0 << 7);
                    int a1 = (s1 + 64) >> 7, b1 = s1 - (a1 << 7);
                    uint32_t* a2w = (uint32_t*)g_A2 + (((size_t)rr * FF + f) * 1024 + c0) / 2;
                    a2w[0]   = bf16bits(a0) | (bf16bits(a1) << 16);
                    a2w[256] = bf16bits(b0) | (bf16bits(b1) << 16);
                } else if (MODE == 2) {
                    *(float2*)(g_sim + ((size_t)rr * FF + f) * MM + c0) = make_float2(v0, v1);
                } else {
                    uint32_t w = sgn_bf16(v0) | (sgn_bf16(v1) << 16);
                    uint32_t* ew = (uint32_t*)g_est + (((size_t)rr * FF + f) * DD + c0) / 2;
                    if (*ew != w) mydiff = 1;
                    *ew = w;
                }
            }
        }
    }
    if (MODE == 3) {
        if (mydiff) sdiff = 1;      // benign same-value race
        __syncthreads();
        if (tid == 0 && sdiff) atomicOr(&g_notconv[it], 1);
    }
}

// ---------------- finalize ----------------
__global__ void k_final(float* __restrict__ out) {
    int gt = blockIdx.x * blockDim.x + threadIdx.x;
    int w = gt >> 5;
    int lane = gt & 31;
    if (w < BB * FF) {
        const float* srow = g_sim + (size_t)w * MM;
        float bestv = -1.f;
        int bestm = 0;
#pragma unroll
        for (int j = 0; j < MM / 32; j++) {
            int m = j * 32 + lane;
            float v = fabsf(srow[m]);
            if (v > bestv) { bestv = v; bestm = m; }
        }
#pragma unroll
        for (int o = 16; o; o >>= 1) {
            float ov = __shfl_down_sync(0xFFFFFFFFu, bestv, o);
            int om = __shfl_down_sync(0xFFFFFFFFu, bestm, o);
            if (ov > bestv || (ov == bestv && om < bestm)) { bestv = ov; bestm = om; }
        }
        if (lane == 0) out[w] = (float)bestm;
    }
    if (blockIdx.x == 0 && threadIdx.x == 0) {
        int k = 0;
        bool done = false;
#pragma unroll
        for (int i = 0; i < RITERS; i++) {
            if (!done) k++;
            if (g_notconv[i] == 0) done = true;
        }
        out[BB * FF] = (float)k;
    }
}

// est (bf16 +-1) -> float out. Out base at float offset 4097 (only 4B aligned) -> scalar stores.
__global__ void k_est_out(float* __restrict__ out) {
    int t = blockIdx.x * blockDim.x + threadIdx.x;
    if (t >= BB * FF * DD / 4) return;
    uint2 w = ((const uint2*)g_est)[t];
    float* o = out + (size_t)(BB * FF) + 1 + (size_t)t * 4;
    o[0] = (w.x & 0x8000u) ? -1.f : 1.f;
    o[1] = (w.x & 0x80000000u) ? -1.f : 1.f;
    o[2] = (w.y & 0x8000u) ? -1.f : 1.f;
    o[3] = (w.y & 0x80000000u) ? -1.f : 1.f;
}

// ---------------- launch ----------------
extern "C" void kernel_launch(void* const* d_in, const int* in_sizes, int n_in,
                              void* d_out, int out_size) {
    const float* inp  = (const float*)d_in[0];
    const float* init = (const float*)d_in[1];
    const float* code = (const float*)d_in[2];
    float* out = (float*)d_out;

    cudaFuncSetAttribute(k_gemm<1>, cudaFuncAttributeMaxDynamicSharedMemorySize, SMEM_DYN);
    cudaFuncSetAttribute(k_gemm<2>, cudaFuncAttributeMaxDynamicSharedMemorySize, SMEM_DYN);
    cudaFuncSetAttribute(k_gemm<3>, cudaFuncAttributeMaxDynamicSharedMemorySize, SMEM_DYN);

    const int n_inp4 = BB * DD / 4;
    const int n_est4 = BB * FF * DD / 4;

    k_reset<<<1, 32>>>();
    k_cvt_ie<<<(n_inp4 + n_est4 + 255) / 256, 256>>>(inp, init, n_inp4, n_est4);
    k_cvt_code<<<dim3(MM / 32, DD / 32, FF), dim3(32, 8)>>>(code);

    for (int it = 0; it < RITERS; it++) {
        k_stage_x<<<(BB * DD / 4 + 255) / 256, 256>>>();
        k_gemm<1><<<dim3(MM / BLK_N, BB / BLK_M, FF), 256, SMEM_DYN>>>(0);
        k_gemm<3><<<dim3(DD / BLK_N, BB / BLK_M, FF), 256, SMEM_DYN>>>(it);
    }
    k_gemm<2><<<dim3(MM / BLK_N, BB / BLK_M, FF), 256, SMEM_DYN>>>(0);
    k_final<<<(BB * FF * 32 + 255) / 256, 256>>>(out);
    k_est_out<<<(BB * FF * DD / 4 + 255) / 256, 256>>>(out);
}

// round 6
// speedup vs baseline: 1.3599x; 1.0673x over previous
#include <cuda_runtime.h>
#include <cuda_bf16.h>
#include <cstdint>

#define BB 1024
#define FF 4
#define MM 512
#define DD 8192
#define RITERS 10

// ---------------- device scratch (no allocations allowed) ----------------
__device__ __nv_bfloat16 g_inp[BB * DD];                  // 16 MB input signs
__device__ __nv_bfloat16 g_est[BB * FF * DD];             // 64 MB estimates (+-1)
__device__ __nv_bfloat16 g_X  [BB * FF * DD];             // 64 MB stage input
__device__ __nv_bfloat16 g_C1 [FF * MM * DD];             // 32 MB codebook signs [f][m][d]
__device__ __nv_bfloat16 g_B2 [(size_t)FF * DD * 1024];   // 64 MB stacked codebook [f][d][k] (+-128 | +-1)
__device__ __nv_bfloat16 g_A2 [BB * FF * 1024];           // 8 MB  sim split digits [b][f][k]
__device__ float         g_sim[BB * FF * MM];             // 8 MB  final sim
__device__ int           g_notconv[RITERS];

__device__ __forceinline__ uint32_t sgn_bf16(float v) { return (v >= 0.f) ? 0x3F80u : 0xBF80u; }
__device__ __forceinline__ uint32_t bf16bits(int v) {
    __nv_bfloat16 h = __float2bfloat16((float)v);
    return (uint32_t)*reinterpret_cast<unsigned short*>(&h);
}

// ---------------- small kernels ----------------
__global__ void k_reset() {
    if (threadIdx.x < RITERS) g_notconv[threadIdx.x] = 0;
}

__global__ void k_cvt_ie(const float* __restrict__ inp, const float* __restrict__ init,
                         int n_inp4, int n_est4) {
    int t = blockIdx.x * blockDim.x + threadIdx.x;
    if (t < n_inp4) {
        float4 v = ((const float4*)inp)[t];
        uint2 w;
        w.x = sgn_bf16(v.x) | (sgn_bf16(v.y) << 16);
        w.y = sgn_bf16(v.z) | (sgn_bf16(v.w) << 16);
        ((uint2*)g_inp)[t] = w;
    } else if (t < n_inp4 + n_est4) {
        int u = t - n_inp4;
        float4 v = ((const float4*)init)[u];
        uint2 w;
        w.x = sgn_bf16(v.x) | (sgn_bf16(v.y) << 16);
        w.y = sgn_bf16(v.z) | (sgn_bf16(v.w) << 16);
        ((uint2*)g_est)[u] = w;
    }
}

// codebook -> C1 [f][m][d] signs AND B2 [f][d][k] (k<512: +-128, k>=512: +-1)
__global__ void k_cvt_code(const float* __restrict__ code) {
    __shared__ unsigned short s[32][33];
    int f = blockIdx.z;
    int m0 = blockIdx.x * 32;
    int d0 = blockIdx.y * 32;
    int tx = threadIdx.x;
    int ty = threadIdx.y;
#pragma unroll
    for (int r = 0; r < 4; r++) {
        int m = m0 + ty + r * 8;
        float v = code[((size_t)(f * MM + m)) * DD + d0 + tx];
        unsigned short sg = (v >= 0.f) ? 0x3F80u : 0xBF80u;
        s[ty + r * 8][tx] = sg;
        *(unsigned short*)&g_C1[((size_t)(f * MM + m)) * DD + d0 + tx] = sg;
    }
    __syncthreads();
#pragma unroll
    for (int r = 0; r < 4; r++) {
        int d = d0 + ty + r * 8;
        unsigned short sg = s[tx][ty + r * 8];
        unsigned short neg = sg >> 15;
        size_t base = ((size_t)f * DD + d) * 1024;
        *(unsigned short*)&g_B2[base + m0 + tx]       = neg ? 0xC300u : 0x4300u;  // +-128
        *(unsigned short*)&g_B2[base + 512 + m0 + tx] = sg;                        // +-1
    }
}

// X[b][f][d] = input * prod_all * est_f  (sign-bit algebra on packed bf16 pairs)
__global__ void k_stage_x() {
    int t = blockIdx.x * blockDim.x + threadIdx.x;
    if (t >= BB * DD / 4) return;
    int b = t / (DD / 4);
    int dq = t % (DD / 4);
    const uint2* inp2 = (const uint2*)g_inp;
    const uint2* est2 = (const uint2*)g_est;
    uint2* x2 = (uint2*)g_X;
    uint2 wi = inp2[(size_t)b * (DD / 4) + dq];
    uint2 e[FF];
#pragma unroll
    for (int f = 0; f < FF; f++)
        e[f] = est2[((size_t)(b * FF + f)) * (DD / 4) + dq];
    uint32_t qx = wi.x ^ e[0].x ^ e[1].x ^ e[2].x ^ e[3].x;
    uint32_t qy = wi.y ^ e[0].y ^ e[1].y ^ e[2].y ^ e[3].y;
#pragma unroll
    for (int f = 0; f < FF; f++) {
        uint2 r;
        r.x = ((qx ^ e[f].x) & 0x80008000u) | 0x3F803F80u;
        r.y = ((qy ^ e[f].y) & 0x80008000u) | 0x3F803F80u;
        x2[((size_t)(b * FF + f)) * (DD / 4) + dq] = r;
    }
}

// ---------------- bf16 mma.sync GEMM with ldmatrix + 3-stage cp.async ----------------
// D[128x128] = A[128xK] * B[128xK]^T
// MODE 1: sim = X*C1^T   (K=8192), epilogue 128-split -> g_A2
// MODE 2: sim = est*C1^T (K=8192), epilogue -> g_sim (float)
// MODE 3: Y  = A2*B2^T   (K=1024), epilogue sign -> g_est + conv flag
#define BLK_M 128
#define BLK_N 128
#define RSTRIDE 144                    // 64 bf16 = 128B data + 16B pad (LDSM conflict-free)
#define A_SZ (BLK_M * RSTRIDE)
#define STG_SZ (2 * A_SZ)
#define NSTAGE 3
#define SMEM_DYN (NSTAGE * STG_SZ)

__device__ __forceinline__ void mma_bf16(float* c, const uint32_t* a, const uint32_t* b) {
    asm volatile(
        "mma.sync.aligned.m16n8k16.row.col.f32.bf16.bf16.f32 "
        "{%0,%1,%2,%3}, {%4,%5,%6,%7}, {%8,%9}, {%0,%1,%2,%3};\n"
        : "+f"(c[0]), "+f"(c[1]), "+f"(c[2]), "+f"(c[3])
        : "r"(a[0]), "r"(a[1]), "r"(a[2]), "r"(a[3]), "r"(b[0]), "r"(b[1]));
}
__device__ __forceinline__ void ldsm4(uint32_t& r0, uint32_t& r1, uint32_t& r2, uint32_t& r3,
                                      uint32_t addr) {
    asm volatile("ldmatrix.sync.aligned.m8n8.x4.shared.b16 {%0,%1,%2,%3}, [%4];"
                 : "=r"(r0), "=r"(r1), "=r"(r2), "=r"(r3) : "r"(addr));
}

template <int MODE>
__global__ void __launch_bounds__(256, 2) k_gemm(int it) {
    extern __shared__ char dsm[];
    __shared__ int sdiff;
    const int tid = threadIdx.x;
    const int lane = tid & 31;
    const int wid = tid >> 5;
    const int wm = wid >> 1, wn = wid & 1;  // 4x2 warps; warp tile 32x64
    const int f = blockIdx.z;
    const int rowBase = blockIdx.y * BLK_M;
    const int colBase = blockIdx.x * BLK_N;

    const char* Ap;
    const char* Bp;
    size_t ldaB, ldbB;
    constexpr int K = (MODE == 3) ? 1024 : DD;
    constexpr int KC = K / 64;
    if (MODE == 1)      { Ap = (const char*)(g_X   + (size_t)f * DD);        ldaB = (size_t)FF * DD * 2;
                          Bp = (const char*)(g_C1  + (size_t)f * MM * DD);   ldbB = (size_t)DD * 2; }
    else if (MODE == 2) { Ap = (const char*)(g_est + (size_t)f * DD);        ldaB = (size_t)FF * DD * 2;
                          Bp = (const char*)(g_C1  + (size_t)f * MM * DD);   ldbB = (size_t)DD * 2; }
    else                { Ap = (const char*)(g_A2  + (size_t)f * 1024);      ldaB = (size_t)FF * 1024 * 2;
                          Bp = (const char*)(g_B2  + (size_t)f * DD * 1024); ldbB = 1024 * 2; }

    if (tid == 0) sdiff = 0;

    const uint32_t smemBase = (uint32_t)__cvta_generic_to_shared(dsm);
    // LDSM lane address offsets (bytes within a stage)
    const uint32_t aoff = (wm * 32 + ((lane >> 3) & 1) * 8 + (lane & 7)) * RSTRIDE + (lane >> 4) * 16;
    const uint32_t boff = A_SZ + (wn * 64 + (lane >> 4) * 8 + (lane & 7)) * RSTRIDE + ((lane >> 3) & 1) * 16;

    auto load_stage = [&](int s, int c) {
        const size_t k0 = (size_t)c * 128;            // bytes
        char* ab = dsm + s * STG_SZ;
        char* bb = ab + A_SZ;
#pragma unroll
        for (int i = 0; i < 4; i++) {                 // A: 1024 chunks of 16B
            int cid = tid + i * 256;
            int r = cid >> 3, sg = cid & 7;
            const char* g = Ap + (size_t)(rowBase + r) * ldaB + k0 + sg * 16;
            uint32_t sa = (uint32_t)__cvta_generic_to_shared(ab + r * RSTRIDE + sg * 16);
            asm volatile("cp.async.cg.shared.global [%0], [%1], 16;" :: "r"(sa), "l"(g));
        }
#pragma unroll
        for (int i = 0; i < 4; i++) {                 // B: 1024 chunks of 16B
            int cid = tid + i * 256;
            int r = cid >> 3, sg = cid & 7;
            const char* g = Bp + (size_t)(colBase + r) * ldbB + k0 + sg * 16;
            uint32_t sa = (uint32_t)__cvta_generic_to_shared(bb + r * RSTRIDE + sg * 16);
            asm volatile("cp.async.cg.shared.global [%0], [%1], 16;" :: "r"(sa), "l"(g));
        }
        asm volatile("cp.async.commit_group;");
    };

    float acc[2][8][4];
#pragma unroll
    for (int mi = 0; mi < 2; mi++)
#pragma unroll
        for (int ni = 0; ni < 8; ni++)
#pragma unroll
            for (int j = 0; j < 4; j++) acc[mi][ni][j] = 0.f;

    load_stage(0, 0);
    load_stage(1, 1);
    int sc = 0, sl = 2;
#pragma unroll 1
    for (int c = 0; c < KC; c++) {
        if (c + 1 < KC) asm volatile("cp.async.wait_group 1;");
        else            asm volatile("cp.async.wait_group 0;");
        __syncthreads();
        const uint32_t sb = smemBase + sc * STG_SZ;
#pragma unroll
        for (int ks = 0; ks < 4; ks++) {
            const uint32_t co = ks * 32;
            uint32_t af[2][4], bf[8][2];
#pragma unroll
            for (int mi = 0; mi < 2; mi++)
                ldsm4(af[mi][0], af[mi][1], af[mi][2], af[mi][3],
                      sb + aoff + mi * 16 * RSTRIDE + co);
#pragma unroll
            for (int p = 0; p < 4; p++)
                ldsm4(bf[2 * p][0], bf[2 * p][1], bf[2 * p + 1][0], bf[2 * p + 1][1],
                      sb + boff + p * 16 * RSTRIDE + co);
#pragma unroll
            for (int mi = 0; mi < 2; mi++)
#pragma unroll
                for (int ni = 0; ni < 8; ni++)
                    mma_bf16(acc[mi][ni], af[mi], bf[ni]);
        }
        if (c + 2 < KC) {
            load_stage(sl, c + 2);
            if (++sl == NSTAGE) sl = 0;
        }
        if (++sc == NSTAGE) sc = 0;
    }

    // ---------------- epilogue (packed 4B/8B coalesced stores) ----------------
    int mydiff = 0;
#pragma unroll
    for (int mi = 0; mi < 2; mi++) {
#pragma unroll
        for (int ni = 0; ni < 8; ni++) {
            const int r0 = rowBase + wm * 32 + mi * 16 + (lane >> 2);
            const int c0 = colBase + wn * 64 + ni * 8 + (lane & 3) * 2;
#pragma unroll
            for (int h = 0; h < 2; h++) {
                const int rr = r0 + h * 8;
                const float v0 = acc[mi][ni][2 * h];
                const float v1 = acc[mi][ni][2 * h + 1];
                if (MODE == 1) {
                    int s0 = __float2int_rn(v0);
                    int s1 = __float2int_rn(v1);
                    int a0 = (s0 + 64) >> 7, b0 = s0 - (a0 << 7);
                    int a1 = (s1 + 64) >> 7, b1 = s1 - (a1 << 7);
                    uint32_t* a2w = (uint32_t*)g_A2 + (((size_t)rr * FF + f) * 1024 + c0) / 2;
                    a2w[0]   = bf16bits(a0) | (bf16bits(a1) << 16);
                    a2w[256] = bf16bits(b0) | (bf16bits(b1) << 16);
                } else if (MODE == 2) {
                    *(float2*)(g_sim + ((size_t)rr * FF + f) * MM + c0) = make_float2(v0, v1);
                } else {
                    uint32_t w = sgn_bf16(v0) | (sgn_bf16(v1) << 16);
                    uint32_t* ew = (uint32_t*)g_est + (((size_t)rr * FF + f) * DD + c0) / 2;
                    if (*ew != w) mydiff = 1;
                    *ew = w;
                }
            }
        }
    }
    if (MODE == 3) {
        if (mydiff) sdiff = 1;      // benign same-value race
        __syncthreads();
        if (tid == 0 && sdiff) atomicOr(&g_notconv[it], 1);
    }
}

// ---------------- finalize ----------------
__global__ void k_final(float* __restrict__ out) {
    int gt = blockIdx.x * blockDim.x + threadIdx.x;
    int w = gt >> 5;
    int lane = gt & 31;
    if (w < BB * FF) {
        const float* srow = g_sim + (size_t)w * MM;
        float bestv = -1.f;
        int bestm = 0;
#pragma unroll
        for (int j = 0; j < MM / 32; j++) {
            int m = j * 32 + lane;
            float v = fabsf(srow[m]);
            if (v > bestv) { bestv = v; bestm = m; }
        }
#pragma unroll
        for (int o = 16; o; o >>= 1) {
            float ov = __shfl_down_sync(0xFFFFFFFFu, bestv, o);
            int om = __shfl_down_sync(0xFFFFFFFFu, bestm, o);
            if (ov > bestv || (ov == bestv && om < bestm)) { bestv = ov; bestm = om; }
        }
        if (lane == 0) out[w] = (float)bestm;
    }
    if (blockIdx.x == 0 && threadIdx.x == 0) {
        int k = 0;
        bool done = false;
#pragma unroll
        for (int i = 0; i < RITERS; i++) {
            if (!done) k++;
            if (g_notconv[i] == 0) done = true;
        }
        out[BB * FF] = (float)k;
    }
}

// est (bf16 +-1) -> float out. Out base at float offset 4097 (only 4B aligned) -> scalar stores.
__global__ void k_est_out(float* __restrict__ out) {
    int t = blockIdx.x * blockDim.x + threadIdx.x;
    if (t >= BB * FF * DD / 4) return;
    uint2 w = ((const uint2*)g_est)[t];
    float* o = out + (size_t)(BB * FF) + 1 + (size_t)t * 4;
    o[0] = (w.x & 0x8000u) ? -1.f : 1.f;
    o[1] = (w.x & 0x80000000u) ? -1.f : 1.f;
    o[2] = (w.y & 0x8000u) ? -1.f : 1.f;
    o[3] = (w.y & 0x80000000u) ? -1.f : 1.f;
}

// ---------------- launch ----------------
extern "C" void kernel_launch(void* const* d_in, const int* in_sizes, int n_in,
                              void* d_out, int out_size) {
    const float* inp  = (const float*)d_in[0];
    const float* init = (const float*)d_in[1];
    const float* code = (const float*)d_in[2];
    float* out = (float*)d_out;

    cudaFuncSetAttribute(k_gemm<1>, cudaFuncAttributeMaxDynamicSharedMemorySize, SMEM_DYN);
    cudaFuncSetAttribute(k_gemm<2>, cudaFuncAttributeMaxDynamicSharedMemorySize, SMEM_DYN);
    cudaFuncSetAttribute(k_gemm<3>, cudaFuncAttributeMaxDynamicSharedMemorySize, SMEM_DYN);

    const int n_inp4 = BB * DD / 4;
    const int n_est4 = BB * FF * DD / 4;

    // Launch order puts iter0's k_gemm<1> at launch index 3 (the ncu capture slot).
    k_cvt_ie<<<(n_inp4 + n_est4 + 255) / 256, 256>>>(inp, init, n_inp4, n_est4);   // 0
    k_cvt_code<<<dim3(MM / 32, DD / 32, FF), dim3(32, 8)>>>(code);                 // 1
    k_stage_x<<<(BB * DD / 4 + 255) / 256, 256>>>();                               // 2
    k_gemm<1><<<dim3(MM / BLK_N, BB / BLK_M, FF), 256, SMEM_DYN>>>(0);             // 3  <- ncu
    k_reset<<<1, 32>>>();                                                          // 4
    k_gemm<3><<<dim3(DD / BLK_N, BB / BLK_M, FF), 256, SMEM_DYN>>>(0);             // 5

    for (int it = 1; it < RITERS; it++) {
        k_stage_x<<<(BB * DD / 4 + 255) / 256, 256>>>();
        k_gemm<1><<<dim3(MM / BLK_N, BB / BLK_M, FF), 256, SMEM_DYN>>>(0);
        k_gemm<3><<<dim3(DD / BLK_N, BB / BLK_M, FF), 256, SMEM_DYN>>>(it);
    }
    k_gemm<2><<<dim3(MM / BLK_N, BB / BLK_M, FF), 256, SMEM_DYN>>>(0);
    k_final<<<(BB * FF * 32 + 255) / 256, 256>>>(out);
    k_est_out<<<(BB * FF * DD / 4 + 255) / 256, 256>>>(out);
}